// round 8
// baseline (speedup 1.0000x reference)
#include <cuda_runtime.h>
#include <cuda_bf16.h>
#include <cstdint>

// DynamicSparseAttention: B=4,H=16,S=2048,D=64
// d_out layout (f32): [out: BH*S*D][attn: BH*S*S][tau: BH*S]
#define S_LEN 2048
#define D_DIM 64
#define BH    64

// ---------------------------------------------------------------- helpers
__device__ __forceinline__ uint32_t smem_u32(const void* p) {
    uint32_t a;
    asm("{ .reg .u64 t; cvta.to.shared.u64 t, %1; cvt.u32.u64 %0, t; }"
        : "=r"(a) : "l"(p));
    return a;
}

// 128B-row tile, 16B-chunk XOR swizzle: offset of (row, chunk16B)
__device__ __forceinline__ uint32_t toff(int r, int ch) {
    return (uint32_t)(r * 128 + ((ch ^ (r & 7)) << 4));
}

__device__ __forceinline__ void ldmx4(uint32_t* r, uint32_t a) {
    asm volatile("ldmatrix.sync.aligned.m8n8.x4.shared.b16 {%0,%1,%2,%3}, [%4];"
        : "=r"(r[0]), "=r"(r[1]), "=r"(r[2]), "=r"(r[3]) : "r"(a));
}
__device__ __forceinline__ void ldmx4t(uint32_t* r, uint32_t a) {
    asm volatile("ldmatrix.sync.aligned.m8n8.x4.trans.shared.b16 {%0,%1,%2,%3}, [%4];"
        : "=r"(r[0]), "=r"(r[1]), "=r"(r[2]), "=r"(r[3]) : "r"(a));
}
__device__ __forceinline__ void mma_bf16(float* c, const uint32_t* a, const uint32_t* b) {
    asm volatile(
        "mma.sync.aligned.m16n8k16.row.col.f32.bf16.bf16.f32 "
        "{%0,%1,%2,%3}, {%4,%5,%6,%7}, {%8,%9}, {%0,%1,%2,%3};"
        : "+f"(c[0]), "+f"(c[1]), "+f"(c[2]), "+f"(c[3])
        : "r"(a[0]), "r"(a[1]), "r"(a[2]), "r"(a[3]), "r"(b[0]), "r"(b[1]));
}

__device__ __forceinline__ uint32_t bfpair(float a, float b) {
    __nv_bfloat162 t;
    t.x = __float2bfloat16(a);
    t.y = __float2bfloat16(b);
    return *reinterpret_cast<uint32_t*>(&t);
}
// split 8 floats into 8 bf16 hi (uint4) + 8 bf16 lo (uint4)
__device__ __forceinline__ void pack8(const float* f, uint4& hi, uint4& lo) {
    float r[8];
    #pragma unroll
    for (int j = 0; j < 8; j++)
        r[j] = f[j] - __bfloat162float(__float2bfloat16(f[j]));
    hi = make_uint4(bfpair(f[0], f[1]), bfpair(f[2], f[3]),
                    bfpair(f[4], f[5]), bfpair(f[6], f[7]));
    lo = make_uint4(bfpair(r[0], r[1]), bfpair(r[2], r[3]),
                    bfpair(r[4], r[5]), bfpair(r[6], r[7]));
}

// -------------------------------------------------------------------------
// Kernel 1: scores = (Q*scale) K^T via mma.sync bf16 hi/lo 3-term split.
// CTA: 128q x 128k, K=64. 8 warps (4m x 2n), warp tile 32x64.
// Dynamic SMEM 64KB: QHI 16K | QLO 16K | KHI 16K | KLO 16K.
// -------------------------------------------------------------------------
#define SC_SMEM 65536
__global__ __launch_bounds__(256) void dsa_scores_kernel(
    const float* __restrict__ q, const float* __restrict__ k,
    float* __restrict__ attn)
{
    extern __shared__ __align__(16) char sm[];
    const uint32_t QHI = 0, QLO = 16384, KHI = 32768, KLO = 49152;
    const uint32_t sb = smem_u32(sm);

    const int tid = threadIdx.x, lane = tid & 31, wid = tid >> 5;
    const int bh = blockIdx.z, qt = blockIdx.y, kt = blockIdx.x;

    const float* Qb = q + ((size_t)bh * S_LEN + (size_t)qt * 128) * D_DIM;
    const float* Kb = k + ((size_t)bh * S_LEN + (size_t)kt * 128) * D_DIM;

    // Q: 128 rows x 8 chunks of 8 floats, scaled by 0.125 (exact pow2)
    #pragma unroll
    for (int i = 0; i < 4; i++) {
        int idx = tid + i * 256;
        int r = idx >> 3, ch = idx & 7;
        float4 f0 = *(const float4*)(Qb + r * D_DIM + ch * 8);
        float4 f1 = *(const float4*)(Qb + r * D_DIM + ch * 8 + 4);
        float f[8] = {f0.x*0.125f, f0.y*0.125f, f0.z*0.125f, f0.w*0.125f,
                      f1.x*0.125f, f1.y*0.125f, f1.z*0.125f, f1.w*0.125f};
        uint4 hi, lo; pack8(f, hi, lo);
        uint32_t o = toff(r, ch);
        *(uint4*)(sm + QHI + o) = hi;
        *(uint4*)(sm + QLO + o) = lo;
    }
    // K: 128 rows x 8 chunks
    #pragma unroll
    for (int i = 0; i < 4; i++) {
        int idx = tid + i * 256;
        int r = idx >> 3, ch = idx & 7;
        float4 f0 = *(const float4*)(Kb + r * D_DIM + ch * 8);
        float4 f1 = *(const float4*)(Kb + r * D_DIM + ch * 8 + 4);
        float f[8] = {f0.x, f0.y, f0.z, f0.w, f1.x, f1.y, f1.z, f1.w};
        uint4 hi, lo; pack8(f, hi, lo);
        uint32_t o = toff(r, ch);
        *(uint4*)(sm + KHI + o) = hi;
        *(uint4*)(sm + KLO + o) = lo;
    }
    __syncthreads();

    const int wm = wid >> 1, wn = wid & 1;
    // A ldmatrix x4 lane mapping
    const int alr = lane & 7, alm = (lane >> 3) & 1, alk = lane >> 4;
    // B ldmatrix x4 lane mapping: two n8 frags per x4, same k16
    const int brow_off = ((lane >> 4) << 3) + (lane & 7);
    const int bchk_off = (lane >> 3) & 1;

    float acc[2][8][4] = {};

    #pragma unroll
    for (int ks = 0; ks < 4; ks++) {
        uint32_t ah[2][4], al[2][4];
        #pragma unroll
        for (int mi = 0; mi < 2; mi++) {
            int row = wm * 32 + mi * 16 + alr + alm * 8;
            uint32_t o = toff(row, ks * 2 + alk);
            ldmx4(ah[mi], sb + QHI + o);
            ldmx4(al[mi], sb + QLO + o);
        }
        #pragma unroll
        for (int nj = 0; nj < 4; nj++) {
            uint32_t bhp[4], blp[4];
            int row = wn * 64 + nj * 16 + brow_off;
            uint32_t o = toff(row, ks * 2 + bchk_off);
            ldmx4(bhp, sb + KHI + o);
            ldmx4(blp, sb + KLO + o);
            #pragma unroll
            for (int mi = 0; mi < 2; mi++) {
                mma_bf16(acc[mi][2*nj],   ah[mi], bhp);
                mma_bf16(acc[mi][2*nj],   ah[mi], blp);
                mma_bf16(acc[mi][2*nj],   al[mi], bhp);
                mma_bf16(acc[mi][2*nj+1], ah[mi], bhp + 2);
                mma_bf16(acc[mi][2*nj+1], ah[mi], blp + 2);
                mma_bf16(acc[mi][2*nj+1], al[mi], bhp + 2);
            }
        }
    }

    const int qr = lane >> 2, qc = (lane & 3) * 2;
    float* base = attn + ((size_t)bh * S_LEN + (size_t)qt * 128) * S_LEN
                       + (size_t)kt * 128;
    #pragma unroll
    for (int mi = 0; mi < 2; mi++) {
        #pragma unroll
        for (int ni = 0; ni < 8; ni++) {
            int row = wm * 32 + mi * 16 + qr;
            int col = wn * 64 + ni * 8 + qc;
            float2 v0 = make_float2(acc[mi][ni][0], acc[mi][ni][1]);
            float2 v1 = make_float2(acc[mi][ni][2], acc[mi][ni][3]);
            *(float2*)(base + (size_t)row * S_LEN + col) = v0;
            *(float2*)(base + (size_t)(row + 8) * S_LEN + col) = v1;
        }
    }
}

// -------------------------------------------------------------------------
// Kernel 2: per-row variance (ddof=1) -> tau -> softmax(scores/tau) in place.
// -------------------------------------------------------------------------
__global__ __launch_bounds__(256) void dsa_softvar_kernel(
    float* __restrict__ attn, float* __restrict__ tau_out)
{
    __shared__ float s[S_LEN];
    __shared__ float redA[8], redB[8], redC[8];
    __shared__ float bc[2];

    const size_t row = blockIdx.x;
    float* rowp = attn + row * (size_t)S_LEN;
    const int tid = threadIdx.x;
    const int lane = tid & 31, wid = tid >> 5;

    float4* s4 = (float4*)s;
    float4* r4 = (float4*)rowp;

    float sum = 0.f, sq = 0.f, mx = -3.402823466e38f;
    #pragma unroll
    for (int i = 0; i < 2; i++) {
        float4 f = r4[tid + i * 256];
        s4[tid + i * 256] = f;
        sum += f.x + f.y + f.z + f.w;
        sq = fmaf(f.x, f.x, sq); sq = fmaf(f.y, f.y, sq);
        sq = fmaf(f.z, f.z, sq); sq = fmaf(f.w, f.w, sq);
        mx = fmaxf(mx, fmaxf(fmaxf(f.x, f.y), fmaxf(f.z, f.w)));
    }
    #pragma unroll
    for (int o = 16; o; o >>= 1) {
        sum += __shfl_xor_sync(0xffffffffu, sum, o);
        sq  += __shfl_xor_sync(0xffffffffu, sq, o);
        mx   = fmaxf(mx, __shfl_xor_sync(0xffffffffu, mx, o));
    }
    if (lane == 0) { redA[wid] = sum; redB[wid] = sq; redC[wid] = mx; }
    __syncthreads();

    if (tid == 0) {
        float St = 0.f, Qt = 0.f, Mt = -3.402823466e38f;
        #pragma unroll
        for (int i = 0; i < 8; i++) {
            St += redA[i]; Qt += redB[i]; Mt = fmaxf(Mt, redC[i]);
        }
        float mean = St * (1.0f / S_LEN);
        float var  = (Qt - St * mean) * (1.0f / (S_LEN - 1));  // ddof=1
        float t = 1.0f / (1.0f + var);                          // BASE_TAU=1
        t = fmaxf(t, 0.3f);                                     // MIN_TAU
        bc[0] = 1.0f / t;
        bc[1] = Mt;
        tau_out[row] = t;
    }
    __syncthreads();

    const float itau = bc[0];
    const float m = bc[1];

    float lsum = 0.f;
    #pragma unroll
    for (int i = 0; i < 2; i++) {
        float4 f = s4[tid + i * 256];
        f.x = __expf((f.x - m) * itau);
        f.y = __expf((f.y - m) * itau);
        f.z = __expf((f.z - m) * itau);
        f.w = __expf((f.w - m) * itau);
        s4[tid + i * 256] = f;
        lsum += f.x + f.y + f.z + f.w;
    }
    #pragma unroll
    for (int o = 16; o; o >>= 1) lsum += __shfl_xor_sync(0xffffffffu, lsum, o);
    if (lane == 0) redA[wid] = lsum;
    __syncthreads();
    if (tid == 0) {
        float d = 0.f;
        #pragma unroll
        for (int i = 0; i < 8; i++) d += redA[i];
        bc[0] = 1.0f / d;
    }
    __syncthreads();

    const float rd = bc[0];
    #pragma unroll
    for (int i = 0; i < 2; i++) {
        float4 f = s4[tid + i * 256];
        f.x *= rd; f.y *= rd; f.z *= rd; f.w *= rd;
        r4[tid + i * 256] = f;
    }
}

// -------------------------------------------------------------------------
// Kernel 3: out = attn @ V via mma.sync bf16 hi/lo 3-term split.
// CTA: 128q x 64d, K=2048 in 32 chunks of 64, DOUBLE-BUFFERED SMEM.
// 8 warps (4m x 2n), warp tile 32x32. V frags via ldmatrix.x4.trans
// (two n8k16 frags per instruction).
// Dynamic SMEM 96KB: 2 x [AHI 16K | ALO 16K | VHI 8K | VLO 8K].
// -------------------------------------------------------------------------
#define AV_SMEM 98304
#define AV_BUF  49152

__global__ __launch_bounds__(256) void dsa_av_kernel(
    const float* __restrict__ attn, const float* __restrict__ v,
    float* __restrict__ out)
{
    extern __shared__ __align__(16) char sm[];
    const uint32_t sb = smem_u32(sm);

    const int tid = threadIdx.x, lane = tid & 31, wid = tid >> 5;
    const int bh = blockIdx.y, qt = blockIdx.x;

    const float* Ab = attn + ((size_t)bh * S_LEN + (size_t)qt * 128) * S_LEN;
    const float* Vb = v + (size_t)bh * S_LEN * D_DIM;

    const int wm = wid >> 1, wn = wid & 1;
    const int alr = lane & 7, alm = (lane >> 3) & 1, alk = lane >> 4;
    // V trans-x4 lane mapping: two n8 frags (ni pair) per x4t, same k16
    const int vkr_off = ((lane >> 3) & 1) * 8 + (lane & 7);
    const int vnc_off = lane >> 4;

    float acc[2][4][4] = {};

    // ---- chunk loader: global f32 -> hi/lo bf16 swizzled SMEM ----
    auto load_chunk = [&](int chnk, int buf) {
        char* bp = sm + buf * AV_BUF;
        const int kk = chnk * 64;
        #pragma unroll
        for (int i = 0; i < 4; i++) {           // A: 128 x 64 f32
            int idx = tid + i * 256;
            int r = idx >> 3, ch = idx & 7;
            float4 f0 = *(const float4*)(Ab + (size_t)r * S_LEN + kk + ch * 8);
            float4 f1 = *(const float4*)(Ab + (size_t)r * S_LEN + kk + ch * 8 + 4);
            float f[8] = {f0.x, f0.y, f0.z, f0.w, f1.x, f1.y, f1.z, f1.w};
            uint4 hi, lo; pack8(f, hi, lo);
            uint32_t o = toff(r, ch);
            *(uint4*)(bp + o) = hi;             // AHI at +0
            *(uint4*)(bp + 16384 + o) = lo;     // ALO
        }
        #pragma unroll
        for (int i = 0; i < 2; i++) {           // V: 64 x 64 f32
            int idx = tid + i * 256;
            int r = idx >> 3, ch = idx & 7;
            float4 f0 = *(const float4*)(Vb + (size_t)(kk + r) * D_DIM + ch * 8);
            float4 f1 = *(const float4*)(Vb + (size_t)(kk + r) * D_DIM + ch * 8 + 4);
            float f[8] = {f0.x, f0.y, f0.z, f0.w, f1.x, f1.y, f1.z, f1.w};
            uint4 hi, lo; pack8(f, hi, lo);
            uint32_t o = toff(r, ch);
            *(uint4*)(bp + 32768 + o) = hi;     // VHI
            *(uint4*)(bp + 40960 + o) = lo;     // VLO
        }
    };

    load_chunk(0, 0);
    __syncthreads();

    for (int chnk = 0; chnk < 32; chnk++) {
        if (chnk + 1 < 32) load_chunk(chnk + 1, (chnk + 1) & 1);

        const uint32_t bp = sb + (chnk & 1) * AV_BUF;
        const uint32_t AHI = bp, ALO = bp + 16384, VHI = bp + 32768, VLO = bp + 40960;

        #pragma unroll
        for (int ks = 0; ks < 4; ks++) {
            uint32_t ah[2][4], al[2][4];
            #pragma unroll
            for (int mi = 0; mi < 2; mi++) {
                int row = wm * 32 + mi * 16 + alr + alm * 8;
                uint32_t o = toff(row, ks * 2 + alk);
                ldmx4(ah[mi], AHI + o);
                ldmx4(al[mi], ALO + o);
            }
            #pragma unroll
            for (int nj = 0; nj < 2; nj++) {
                uint32_t bhp[4], blp[4];
                int krow = ks * 16 + vkr_off;
                int nc = wn * 4 + nj * 2 + vnc_off;
                uint32_t o = toff(krow, nc);
                ldmx4t(bhp, VHI + o);
                ldmx4t(blp, VLO + o);
                #pragma unroll
                for (int mi = 0; mi < 2; mi++) {
                    mma_bf16(acc[mi][2*nj],   ah[mi], bhp);
                    mma_bf16(acc[mi][2*nj],   ah[mi], blp);
                    mma_bf16(acc[mi][2*nj],   al[mi], bhp);
                    mma_bf16(acc[mi][2*nj+1], ah[mi], bhp + 2);
                    mma_bf16(acc[mi][2*nj+1], ah[mi], blp + 2);
                    mma_bf16(acc[mi][2*nj+1], al[mi], bhp + 2);
                }
            }
        }
        __syncthreads();
    }

    const int qr = lane >> 2, qc = (lane & 3) * 2;
    float* Ob = out + ((size_t)bh * S_LEN + (size_t)qt * 128) * D_DIM;
    #pragma unroll
    for (int mi = 0; mi < 2; mi++) {
        #pragma unroll
        for (int ni = 0; ni < 4; ni++) {
            int row = wm * 32 + mi * 16 + qr;
            int col = wn * 32 + ni * 8 + qc;
            float2 v0 = make_float2(acc[mi][ni][0], acc[mi][ni][1]);
            float2 v1 = make_float2(acc[mi][ni][2], acc[mi][ni][3]);
            *(float2*)(Ob + (size_t)row * D_DIM + col) = v0;
            *(float2*)(Ob + (size_t)(row + 8) * D_DIM + col) = v1;
        }
    }
}

// -------------------------------------------------------------------------
extern "C" void kernel_launch(void* const* d_in, const int* in_sizes, int n_in,
                              void* d_out, int out_size)
{
    const float* q = (const float*)d_in[0];
    const float* k = (const float*)d_in[1];
    const float* v = (const float*)d_in[2];

    float* outp = (float*)d_out;                                   // BH*S*D
    float* attn = outp + (size_t)BH * S_LEN * D_DIM;               // BH*S*S
    float* tau  = attn + (size_t)BH * S_LEN * S_LEN;               // BH*S

    cudaFuncSetAttribute(dsa_scores_kernel,
                         cudaFuncAttributeMaxDynamicSharedMemorySize, SC_SMEM);
    cudaFuncSetAttribute(dsa_av_kernel,
                         cudaFuncAttributeMaxDynamicSharedMemorySize, AV_SMEM);

    dsa_scores_kernel<<<dim3(S_LEN/128, S_LEN/128, BH), 256, SC_SMEM>>>(q, k, attn);
    dsa_softvar_kernel<<<BH * S_LEN, 256>>>(attn, tau);
    dsa_av_kernel<<<dim3(S_LEN/128, BH), 256, AV_SMEM>>>(attn, v, outp);
}

// round 9
// speedup vs baseline: 1.0392x; 1.0392x over previous
#include <cuda_runtime.h>
#include <cuda_bf16.h>
#include <cstdint>

// DynamicSparseAttention: B=4,H=16,S=2048,D=64
// d_out layout (f32): [out: BH*S*D][attn: BH*S*S][tau: BH*S]
#define S_LEN 2048
#define D_DIM 64
#define BH    64

// ---------------------------------------------------------------- helpers
__device__ __forceinline__ uint32_t smem_u32(const void* p) {
    uint32_t a;
    asm("{ .reg .u64 t; cvta.to.shared.u64 t, %1; cvt.u32.u64 %0, t; }"
        : "=r"(a) : "l"(p));
    return a;
}

// 128B-row tile, 16B-chunk XOR swizzle: offset of (row, chunk16B)
__device__ __forceinline__ uint32_t toff(int r, int ch) {
    return (uint32_t)(r * 128 + ((ch ^ (r & 7)) << 4));
}

__device__ __forceinline__ void ldmx4(uint32_t* r, uint32_t a) {
    asm volatile("ldmatrix.sync.aligned.m8n8.x4.shared.b16 {%0,%1,%2,%3}, [%4];"
        : "=r"(r[0]), "=r"(r[1]), "=r"(r[2]), "=r"(r[3]) : "r"(a));
}
__device__ __forceinline__ void ldmx4t(uint32_t* r, uint32_t a) {
    asm volatile("ldmatrix.sync.aligned.m8n8.x4.trans.shared.b16 {%0,%1,%2,%3}, [%4];"
        : "=r"(r[0]), "=r"(r[1]), "=r"(r[2]), "=r"(r[3]) : "r"(a));
}
__device__ __forceinline__ void mma_bf16(float* c, const uint32_t* a, const uint32_t* b) {
    asm volatile(
        "mma.sync.aligned.m16n8k16.row.col.f32.bf16.bf16.f32 "
        "{%0,%1,%2,%3}, {%4,%5,%6,%7}, {%8,%9}, {%0,%1,%2,%3};"
        : "+f"(c[0]), "+f"(c[1]), "+f"(c[2]), "+f"(c[3])
        : "r"(a[0]), "r"(a[1]), "r"(a[2]), "r"(a[3]), "r"(b[0]), "r"(b[1]));
}

__device__ __forceinline__ uint32_t bfpair(float a, float b) {
    __nv_bfloat162 t;
    t.x = __float2bfloat16(a);
    t.y = __float2bfloat16(b);
    return *reinterpret_cast<uint32_t*>(&t);
}
// split 8 floats into 8 bf16 hi (uint4) + 8 bf16 lo (uint4)
__device__ __forceinline__ void pack8(const float* f, uint4& hi, uint4& lo) {
    float r[8];
    #pragma unroll
    for (int j = 0; j < 8; j++)
        r[j] = f[j] - __bfloat162float(__float2bfloat16(f[j]));
    hi = make_uint4(bfpair(f[0], f[1]), bfpair(f[2], f[3]),
                    bfpair(f[4], f[5]), bfpair(f[6], f[7]));
    lo = make_uint4(bfpair(r[0], r[1]), bfpair(r[2], r[3]),
                    bfpair(r[4], r[5]), bfpair(r[6], r[7]));
}

// -------------------------------------------------------------------------
// Kernel 1: scores = (Q*scale) K^T via mma.sync bf16 hi/lo 3-term split.
// CTA: 128q x 64k, K=64. 8 warps (4m x 2n), warp tile 32x32.
// Term-major mma ordering (8 independent mmas between acc reuses).
// SMEM 48KB static: QHI 16K | QLO 16K | KHI 8K | KLO 8K.  2 CTAs/SM.
// -------------------------------------------------------------------------
__global__ __launch_bounds__(256, 2) void dsa_scores_kernel(
    const float* __restrict__ q, const float* __restrict__ k,
    float* __restrict__ attn)
{
    __shared__ __align__(16) char sm[49152];
    const uint32_t QHI = 0, QLO = 16384, KHI = 32768, KLO = 40960;
    const uint32_t sb = smem_u32(sm);

    const int tid = threadIdx.x, lane = tid & 31, wid = tid >> 5;
    const int bh = blockIdx.z, qt = blockIdx.y, kt = blockIdx.x;

    const float* Qb = q + ((size_t)bh * S_LEN + (size_t)qt * 128) * D_DIM;
    const float* Kb = k + ((size_t)bh * S_LEN + (size_t)kt * 64) * D_DIM;

    // Q: 128 rows x 8 chunks of 8 floats, scaled by 0.125 (exact pow2)
    #pragma unroll
    for (int i = 0; i < 4; i++) {
        int idx = tid + i * 256;
        int r = idx >> 3, ch = idx & 7;
        float4 f0 = *(const float4*)(Qb + r * D_DIM + ch * 8);
        float4 f1 = *(const float4*)(Qb + r * D_DIM + ch * 8 + 4);
        float f[8] = {f0.x*0.125f, f0.y*0.125f, f0.z*0.125f, f0.w*0.125f,
                      f1.x*0.125f, f1.y*0.125f, f1.z*0.125f, f1.w*0.125f};
        uint4 hi, lo; pack8(f, hi, lo);
        uint32_t o = toff(r, ch);
        *(uint4*)(sm + QHI + o) = hi;
        *(uint4*)(sm + QLO + o) = lo;
    }
    // K: 64 rows x 8 chunks
    #pragma unroll
    for (int i = 0; i < 2; i++) {
        int idx = tid + i * 256;
        int r = idx >> 3, ch = idx & 7;
        float4 f0 = *(const float4*)(Kb + r * D_DIM + ch * 8);
        float4 f1 = *(const float4*)(Kb + r * D_DIM + ch * 8 + 4);
        float f[8] = {f0.x, f0.y, f0.z, f0.w, f1.x, f1.y, f1.z, f1.w};
        uint4 hi, lo; pack8(f, hi, lo);
        uint32_t o = toff(r, ch);
        *(uint4*)(sm + KHI + o) = hi;
        *(uint4*)(sm + KLO + o) = lo;
    }
    __syncthreads();

    const int wm = wid >> 1, wn = wid & 1;
    // A ldmatrix x4 lane mapping
    const int alr = lane & 7, alm = (lane >> 3) & 1, alk = lane >> 4;
    // B ldmatrix x4 lane mapping: two n8 frags per x4, same k16
    const int brow_off = ((lane >> 4) << 3) + (lane & 7);
    const int bchk_off = (lane >> 3) & 1;

    float acc[2][4][4] = {};

    #pragma unroll
    for (int ks = 0; ks < 4; ks++) {
        uint32_t ah[2][4], al[2][4];
        #pragma unroll
        for (int mi = 0; mi < 2; mi++) {
            int row = wm * 32 + mi * 16 + alr + alm * 8;
            uint32_t o = toff(row, ks * 2 + alk);
            ldmx4(ah[mi], sb + QHI + o);
            ldmx4(al[mi], sb + QLO + o);
        }
        uint32_t bh_[2][4], bl_[2][4];
        #pragma unroll
        for (int nj = 0; nj < 2; nj++) {
            int row = wn * 32 + nj * 16 + brow_off;
            uint32_t o = toff(row, ks * 2 + bchk_off);
            ldmx4(bh_[nj], sb + KHI + o);
            ldmx4(bl_[nj], sb + KLO + o);
        }
        // term-major: 8 independent mmas per term
        #pragma unroll
        for (int mi = 0; mi < 2; mi++)
            #pragma unroll
            for (int nj = 0; nj < 2; nj++) {
                mma_bf16(acc[mi][2*nj],   ah[mi], bh_[nj]);
                mma_bf16(acc[mi][2*nj+1], ah[mi], bh_[nj] + 2);
            }
        #pragma unroll
        for (int mi = 0; mi < 2; mi++)
            #pragma unroll
            for (int nj = 0; nj < 2; nj++) {
                mma_bf16(acc[mi][2*nj],   ah[mi], bl_[nj]);
                mma_bf16(acc[mi][2*nj+1], ah[mi], bl_[nj] + 2);
            }
        #pragma unroll
        for (int mi = 0; mi < 2; mi++)
            #pragma unroll
            for (int nj = 0; nj < 2; nj++) {
                mma_bf16(acc[mi][2*nj],   al[mi], bh_[nj]);
                mma_bf16(acc[mi][2*nj+1], al[mi], bh_[nj] + 2);
            }
    }

    const int qr = lane >> 2, qc = (lane & 3) * 2;
    float* base = attn + ((size_t)bh * S_LEN + (size_t)qt * 128) * S_LEN
                       + (size_t)kt * 64;
    #pragma unroll
    for (int mi = 0; mi < 2; mi++) {
        #pragma unroll
        for (int ni = 0; ni < 4; ni++) {
            int row = wm * 32 + mi * 16 + qr;
            int col = wn * 32 + ni * 8 + qc;
            float2 v0 = make_float2(acc[mi][ni][0], acc[mi][ni][1]);
            float2 v1 = make_float2(acc[mi][ni][2], acc[mi][ni][3]);
            *(float2*)(base + (size_t)row * S_LEN + col) = v0;
            *(float2*)(base + (size_t)(row + 8) * S_LEN + col) = v1;
        }
    }
}

// -------------------------------------------------------------------------
// Kernel 2: per-row variance (ddof=1) -> tau -> softmax(scores/tau) in place.
// -------------------------------------------------------------------------
__global__ __launch_bounds__(256) void dsa_softvar_kernel(
    float* __restrict__ attn, float* __restrict__ tau_out)
{
    __shared__ float s[S_LEN];
    __shared__ float redA[8], redB[8], redC[8];
    __shared__ float bc[2];

    const size_t row = blockIdx.x;
    float* rowp = attn + row * (size_t)S_LEN;
    const int tid = threadIdx.x;
    const int lane = tid & 31, wid = tid >> 5;

    float4* s4 = (float4*)s;
    float4* r4 = (float4*)rowp;

    float sum = 0.f, sq = 0.f, mx = -3.402823466e38f;
    #pragma unroll
    for (int i = 0; i < 2; i++) {
        float4 f = r4[tid + i * 256];
        s4[tid + i * 256] = f;
        sum += f.x + f.y + f.z + f.w;
        sq = fmaf(f.x, f.x, sq); sq = fmaf(f.y, f.y, sq);
        sq = fmaf(f.z, f.z, sq); sq = fmaf(f.w, f.w, sq);
        mx = fmaxf(mx, fmaxf(fmaxf(f.x, f.y), fmaxf(f.z, f.w)));
    }
    #pragma unroll
    for (int o = 16; o; o >>= 1) {
        sum += __shfl_xor_sync(0xffffffffu, sum, o);
        sq  += __shfl_xor_sync(0xffffffffu, sq, o);
        mx   = fmaxf(mx, __shfl_xor_sync(0xffffffffu, mx, o));
    }
    if (lane == 0) { redA[wid] = sum; redB[wid] = sq; redC[wid] = mx; }
    __syncthreads();

    if (tid == 0) {
        float St = 0.f, Qt = 0.f, Mt = -3.402823466e38f;
        #pragma unroll
        for (int i = 0; i < 8; i++) {
            St += redA[i]; Qt += redB[i]; Mt = fmaxf(Mt, redC[i]);
        }
        float mean = St * (1.0f / S_LEN);
        float var  = (Qt - St * mean) * (1.0f / (S_LEN - 1));  // ddof=1
        float t = 1.0f / (1.0f + var);                          // BASE_TAU=1
        t = fmaxf(t, 0.3f);                                     // MIN_TAU
        bc[0] = 1.0f / t;
        bc[1] = Mt;
        tau_out[row] = t;
    }
    __syncthreads();

    const float itau = bc[0];
    const float m = bc[1];

    float lsum = 0.f;
    #pragma unroll
    for (int i = 0; i < 2; i++) {
        float4 f = s4[tid + i * 256];
        f.x = __expf((f.x - m) * itau);
        f.y = __expf((f.y - m) * itau);
        f.z = __expf((f.z - m) * itau);
        f.w = __expf((f.w - m) * itau);
        s4[tid + i * 256] = f;
        lsum += f.x + f.y + f.z + f.w;
    }
    #pragma unroll
    for (int o = 16; o; o >>= 1) lsum += __shfl_xor_sync(0xffffffffu, lsum, o);
    if (lane == 0) redA[wid] = lsum;
    __syncthreads();
    if (tid == 0) {
        float d = 0.f;
        #pragma unroll
        for (int i = 0; i < 8; i++) d += redA[i];
        bc[0] = 1.0f / d;
    }
    __syncthreads();

    const float rd = bc[0];
    #pragma unroll
    for (int i = 0; i < 2; i++) {
        float4 f = s4[tid + i * 256];
        f.x *= rd; f.y *= rd; f.z *= rd; f.w *= rd;
        r4[tid + i * 256] = f;
    }
}

// -------------------------------------------------------------------------
// Kernel 3: out = attn @ V via mma.sync bf16 hi/lo 3-term split.
// CTA: 128q x 64d, K=2048 in 32 chunks of 64, double-buffered SMEM.
// Term-major mma ordering. V frags via ldmatrix.x4.trans.
// Dynamic SMEM 96KB: 2 x [AHI 16K | ALO 16K | VHI 8K | VLO 8K].
// -------------------------------------------------------------------------
#define AV_SMEM 98304
#define AV_BUF  49152

__global__ __launch_bounds__(256, 2) void dsa_av_kernel(
    const float* __restrict__ attn, const float* __restrict__ v,
    float* __restrict__ out)
{
    extern __shared__ __align__(16) char sm[];
    const uint32_t sb = smem_u32(sm);

    const int tid = threadIdx.x, lane = tid & 31, wid = tid >> 5;
    const int bh = blockIdx.y, qt = blockIdx.x;

    const float* Ab = attn + ((size_t)bh * S_LEN + (size_t)qt * 128) * S_LEN;
    const float* Vb = v + (size_t)bh * S_LEN * D_DIM;

    const int wm = wid >> 1, wn = wid & 1;
    const int alr = lane & 7, alm = (lane >> 3) & 1, alk = lane >> 4;
    // V trans-x4 lane mapping: two n8 frags per x4t, same k16
    const int vkr_off = ((lane >> 3) & 1) * 8 + (lane & 7);
    const int vnc_off = lane >> 4;

    float acc[2][4][4] = {};

    // ---- chunk loader: global f32 -> hi/lo bf16 swizzled SMEM ----
    auto load_chunk = [&](int chnk, int buf) {
        char* bp = sm + buf * AV_BUF;
        const int kk = chnk * 64;
        #pragma unroll
        for (int i = 0; i < 4; i++) {           // A: 128 x 64 f32
            int idx = tid + i * 256;
            int r = idx >> 3, ch = idx & 7;
            float4 f0 = *(const float4*)(Ab + (size_t)r * S_LEN + kk + ch * 8);
            float4 f1 = *(const float4*)(Ab + (size_t)r * S_LEN + kk + ch * 8 + 4);
            float f[8] = {f0.x, f0.y, f0.z, f0.w, f1.x, f1.y, f1.z, f1.w};
            uint4 hi, lo; pack8(f, hi, lo);
            uint32_t o = toff(r, ch);
            *(uint4*)(bp + o) = hi;             // AHI at +0
            *(uint4*)(bp + 16384 + o) = lo;     // ALO
        }
        #pragma unroll
        for (int i = 0; i < 2; i++) {           // V: 64 x 64 f32
            int idx = tid + i * 256;
            int r = idx >> 3, ch = idx & 7;
            float4 f0 = *(const float4*)(Vb + (size_t)(kk + r) * D_DIM + ch * 8);
            float4 f1 = *(const float4*)(Vb + (size_t)(kk + r) * D_DIM + ch * 8 + 4);
            float f[8] = {f0.x, f0.y, f0.z, f0.w, f1.x, f1.y, f1.z, f1.w};
            uint4 hi, lo; pack8(f, hi, lo);
            uint32_t o = toff(r, ch);
            *(uint4*)(bp + 32768 + o) = hi;     // VHI
            *(uint4*)(bp + 40960 + o) = lo;     // VLO
        }
    };

    load_chunk(0, 0);
    __syncthreads();

    for (int chnk = 0; chnk < 32; chnk++) {
        if (chnk + 1 < 32) load_chunk(chnk + 1, (chnk + 1) & 1);

        const uint32_t bp = sb + (chnk & 1) * AV_BUF;
        const uint32_t AHI = bp, ALO = bp + 16384, VHI = bp + 32768, VLO = bp + 40960;

        #pragma unroll
        for (int ks = 0; ks < 4; ks++) {
            uint32_t ah[2][4], al[2][4];
            #pragma unroll
            for (int mi = 0; mi < 2; mi++) {
                int row = wm * 32 + mi * 16 + alr + alm * 8;
                uint32_t o = toff(row, ks * 2 + alk);
                ldmx4(ah[mi], AHI + o);
                ldmx4(al[mi], ALO + o);
            }
            uint32_t vh_[2][4], vl_[2][4];
            #pragma unroll
            for (int nj = 0; nj < 2; nj++) {
                int krow = ks * 16 + vkr_off;
                int nc = wn * 4 + nj * 2 + vnc_off;
                uint32_t o = toff(krow, nc);
                ldmx4t(vh_[nj], VHI + o);
                ldmx4t(vl_[nj], VLO + o);
            }
            // term-major
            #pragma unroll
            for (int mi = 0; mi < 2; mi++)
                #pragma unroll
                for (int nj = 0; nj < 2; nj++) {
                    mma_bf16(acc[mi][2*nj],   ah[mi], vh_[nj]);
                    mma_bf16(acc[mi][2*nj+1], ah[mi], vh_[nj] + 2);
                }
            #pragma unroll
            for (int mi = 0; mi < 2; mi++)
                #pragma unroll
                for (int nj = 0; nj < 2; nj++) {
                    mma_bf16(acc[mi][2*nj],   ah[mi], vl_[nj]);
                    mma_bf16(acc[mi][2*nj+1], ah[mi], vl_[nj] + 2);
                }
            #pragma unroll
            for (int mi = 0; mi < 2; mi++)
                #pragma unroll
                for (int nj = 0; nj < 2; nj++) {
                    mma_bf16(acc[mi][2*nj],   al[mi], vh_[nj]);
                    mma_bf16(acc[mi][2*nj+1], al[mi], vh_[nj] + 2);
                }
        }
        __syncthreads();
    }

    const int qr = lane >> 2, qc = (lane & 3) * 2;
    float* Ob = out + ((size_t)bh * S_LEN + (size_t)qt * 128) * D_DIM;
    #pragma unroll
    for (int mi = 0; mi < 2; mi++) {
        #pragma unroll
        for (int ni = 0; ni < 4; ni++) {
            int row = wm * 32 + mi * 16 + qr;
            int col = wn * 32 + ni * 8 + qc;
            float2 v0 = make_float2(acc[mi][ni][0], acc[mi][ni][1]);
            float2 v1 = make_float2(acc[mi][ni][2], acc[mi][ni][3]);
            *(float2*)(Ob + (size_t)row * D_DIM + col) = v0;
            *(float2*)(Ob + (size_t)(row + 8) * D_DIM + col) = v1;
        }
    }
}

// -------------------------------------------------------------------------
extern "C" void kernel_launch(void* const* d_in, const int* in_sizes, int n_in,
                              void* d_out, int out_size)
{
    const float* q = (const float*)d_in[0];
    const float* k = (const float*)d_in[1];
    const float* v = (const float*)d_in[2];

    float* outp = (float*)d_out;                                   // BH*S*D
    float* attn = outp + (size_t)BH * S_LEN * D_DIM;               // BH*S*S
    float* tau  = attn + (size_t)BH * S_LEN * S_LEN;               // BH*S

    cudaFuncSetAttribute(dsa_av_kernel,
                         cudaFuncAttributeMaxDynamicSharedMemorySize, AV_SMEM);

    dsa_scores_kernel<<<dim3(S_LEN/64, S_LEN/128, BH), 256>>>(q, k, attn);
    dsa_softvar_kernel<<<BH * S_LEN, 256>>>(attn, tau);
    dsa_av_kernel<<<dim3(S_LEN/128, BH), 256, AV_SMEM>>>(attn, v, outp);
}

// round 10
// speedup vs baseline: 1.1292x; 1.0867x over previous
#include <cuda_runtime.h>
#include <cuda_bf16.h>
#include <cstdint>

// DynamicSparseAttention: B=4,H=16,S=2048,D=64
// d_out layout (f32): [out: BH*S*D][attn: BH*S*S][tau: BH*S]
#define S_LEN 2048
#define D_DIM 64
#define BH    64

// ---------------------------------------------------------------- helpers
__device__ __forceinline__ uint32_t smem_u32(const void* p) {
    uint32_t a;
    asm("{ .reg .u64 t; cvta.to.shared.u64 t, %1; cvt.u32.u64 %0, t; }"
        : "=r"(a) : "l"(p));
    return a;
}

// 128B-row tile, 16B-chunk XOR swizzle: offset of (row, chunk16B)
__device__ __forceinline__ uint32_t toff(int r, int ch) {
    return (uint32_t)(r * 128 + ((ch ^ (r & 7)) << 4));
}

__device__ __forceinline__ void ldmx4(uint32_t* r, uint32_t a) {
    asm volatile("ldmatrix.sync.aligned.m8n8.x4.shared.b16 {%0,%1,%2,%3}, [%4];"
        : "=r"(r[0]), "=r"(r[1]), "=r"(r[2]), "=r"(r[3]) : "r"(a));
}
__device__ __forceinline__ void ldmx4t(uint32_t* r, uint32_t a) {
    asm volatile("ldmatrix.sync.aligned.m8n8.x4.trans.shared.b16 {%0,%1,%2,%3}, [%4];"
        : "=r"(r[0]), "=r"(r[1]), "=r"(r[2]), "=r"(r[3]) : "r"(a));
}
__device__ __forceinline__ void mma_bf16(float* c, const uint32_t* a, const uint32_t* b) {
    asm volatile(
        "mma.sync.aligned.m16n8k16.row.col.f32.bf16.bf16.f32 "
        "{%0,%1,%2,%3}, {%4,%5,%6,%7}, {%8,%9}, {%0,%1,%2,%3};"
        : "+f"(c[0]), "+f"(c[1]), "+f"(c[2]), "+f"(c[3])
        : "r"(a[0]), "r"(a[1]), "r"(a[2]), "r"(a[3]), "r"(b[0]), "r"(b[1]));
}

__device__ __forceinline__ uint32_t bfpair(float a, float b) {
    __nv_bfloat162 t;
    t.x = __float2bfloat16(a);
    t.y = __float2bfloat16(b);
    return *reinterpret_cast<uint32_t*>(&t);
}
// split 8 floats into 8 bf16 hi (uint4) + 8 bf16 lo (uint4)
__device__ __forceinline__ void pack8(const float* f, uint4& hi, uint4& lo) {
    float r[8];
    #pragma unroll
    for (int j = 0; j < 8; j++)
        r[j] = f[j] - __bfloat162float(__float2bfloat16(f[j]));
    hi = make_uint4(bfpair(f[0], f[1]), bfpair(f[2], f[3]),
                    bfpair(f[4], f[5]), bfpair(f[6], f[7]));
    lo = make_uint4(bfpair(r[0], r[1]), bfpair(r[2], r[3]),
                    bfpair(r[4], r[5]), bfpair(r[6], r[7]));
}

// -------------------------------------------------------------------------
// Kernel 1: scores = (Q*scale) K^T via mma.sync bf16 hi/lo 3-term split.
// CTA owns a 128-row q-stripe and loops over all 16 k-tiles of 128.
// Q packed once; A fragments CACHED IN REGISTERS for the whole kernel.
// K double-buffered with register-staged prefetch. 8 warps (4m x 2n),
// warp tile 32x64. Dynamic SMEM 96KB: Q(hi/lo 32K) + 2 x K(hi/lo 32K).
// -------------------------------------------------------------------------
#define SC_SMEM 98304
__global__ __launch_bounds__(256) void dsa_scores_kernel(
    const float* __restrict__ q, const float* __restrict__ k,
    float* __restrict__ attn)
{
    extern __shared__ __align__(16) char sm[];
    const uint32_t sb = smem_u32(sm);
    const uint32_t QHI = 0, QLO = 16384;   // K bufs at 32768 + buf*32768

    const int tid = threadIdx.x, lane = tid & 31, wid = tid >> 5;
    const int qt = blockIdx.x, bh = blockIdx.y;

    const float* Qb = q + ((size_t)bh * S_LEN + (size_t)qt * 128) * D_DIM;
    const float* Kbase = k + (size_t)bh * S_LEN * D_DIM;

    // ---- Q: load, scale by 0.125 (exact pow2), split, STS (once) ----
    #pragma unroll
    for (int i = 0; i < 4; i++) {
        int idx = tid + i * 256;
        int r = idx >> 3, ch = idx & 7;
        float4 f0 = *(const float4*)(Qb + r * D_DIM + ch * 8);
        float4 f1 = *(const float4*)(Qb + r * D_DIM + ch * 8 + 4);
        float f[8] = {f0.x*0.125f, f0.y*0.125f, f0.z*0.125f, f0.w*0.125f,
                      f1.x*0.125f, f1.y*0.125f, f1.z*0.125f, f1.w*0.125f};
        uint4 hi, lo; pack8(f, hi, lo);
        uint32_t o = toff(r, ch);
        *(uint4*)(sm + QHI + o) = hi;
        *(uint4*)(sm + QLO + o) = lo;
    }
    __syncthreads();

    const int wm = wid >> 1, wn = wid & 1;
    const int alr = lane & 7, alm = (lane >> 3) & 1, alk = lane >> 4;
    const int brow_off = ((lane >> 4) << 3) + (lane & 7);
    const int bchk_off = (lane >> 3) & 1;

    // ---- A fragments cached in registers for all 4 k-steps ----
    uint32_t ah[4][2][4], al[4][2][4];
    #pragma unroll
    for (int ks = 0; ks < 4; ks++)
        #pragma unroll
        for (int mi = 0; mi < 2; mi++) {
            int row = wm * 32 + mi * 16 + alr + alm * 8;
            uint32_t o = toff(row, ks * 2 + alk);
            ldmx4(ah[ks][mi], sb + QHI + o);
            ldmx4(al[ks][mi], sb + QLO + o);
        }

    // ---- prologue: K tile 0 -> buf 0 ----
    float4 pf[8];
    {
        const float* Kt = Kbase;
        #pragma unroll
        for (int i = 0; i < 4; i++) {
            int idx = tid + i * 256;
            int r = idx >> 3, ch = idx & 7;
            pf[2*i]   = *(const float4*)(Kt + r * D_DIM + ch * 8);
            pf[2*i+1] = *(const float4*)(Kt + r * D_DIM + ch * 8 + 4);
        }
        #pragma unroll
        for (int i = 0; i < 4; i++) {
            int idx = tid + i * 256;
            int r = idx >> 3, ch = idx & 7;
            float f[8] = {pf[2*i].x, pf[2*i].y, pf[2*i].z, pf[2*i].w,
                          pf[2*i+1].x, pf[2*i+1].y, pf[2*i+1].z, pf[2*i+1].w};
            uint4 hi, lo; pack8(f, hi, lo);
            uint32_t o = toff(r, ch);
            *(uint4*)(sm + 32768 + o) = hi;
            *(uint4*)(sm + 32768 + 16384 + o) = lo;
        }
    }
    __syncthreads();

    const int qr = lane >> 2, qc = (lane & 3) * 2;
    float* abase = attn + ((size_t)bh * S_LEN + (size_t)qt * 128) * S_LEN;

    for (int t = 0; t < 16; t++) {
        // prefetch next K tile into registers (hides LDG under mma)
        if (t < 15) {
            const float* Kt = Kbase + (size_t)(t + 1) * 128 * D_DIM;
            #pragma unroll
            for (int i = 0; i < 4; i++) {
                int idx = tid + i * 256;
                int r = idx >> 3, ch = idx & 7;
                pf[2*i]   = *(const float4*)(Kt + r * D_DIM + ch * 8);
                pf[2*i+1] = *(const float4*)(Kt + r * D_DIM + ch * 8 + 4);
            }
        }

        const uint32_t KB = sb + 32768 + (uint32_t)(t & 1) * 32768;

        float acc[2][8][4] = {};
        #pragma unroll
        for (int ks = 0; ks < 4; ks++) {
            uint32_t bh_[4][4], bl_[4][4];
            #pragma unroll
            for (int nj = 0; nj < 4; nj++) {
                int row = wn * 64 + nj * 16 + brow_off;
                uint32_t o = toff(row, ks * 2 + bchk_off);
                ldmx4(bh_[nj], KB + o);
                ldmx4(bl_[nj], KB + 16384 + o);
            }
            // term-major: 16 independent mmas per term
            #pragma unroll
            for (int mi = 0; mi < 2; mi++)
                #pragma unroll
                for (int nj = 0; nj < 4; nj++) {
                    mma_bf16(acc[mi][2*nj],   ah[ks][mi], bh_[nj]);
                    mma_bf16(acc[mi][2*nj+1], ah[ks][mi], bh_[nj] + 2);
                }
            #pragma unroll
            for (int mi = 0; mi < 2; mi++)
                #pragma unroll
                for (int nj = 0; nj < 4; nj++) {
                    mma_bf16(acc[mi][2*nj],   ah[ks][mi], bl_[nj]);
                    mma_bf16(acc[mi][2*nj+1], ah[ks][mi], bl_[nj] + 2);
                }
            #pragma unroll
            for (int mi = 0; mi < 2; mi++)
                #pragma unroll
                for (int nj = 0; nj < 4; nj++) {
                    mma_bf16(acc[mi][2*nj],   al[ks][mi], bh_[nj]);
                    mma_bf16(acc[mi][2*nj+1], al[ks][mi], bh_[nj] + 2);
                }
        }

        // stage next K tile into the other buffer
        if (t < 15) {
            char* bp = sm + 32768 + (size_t)((t + 1) & 1) * 32768;
            #pragma unroll
            for (int i = 0; i < 4; i++) {
                int idx = tid + i * 256;
                int r = idx >> 3, ch = idx & 7;
                float f[8] = {pf[2*i].x, pf[2*i].y, pf[2*i].z, pf[2*i].w,
                              pf[2*i+1].x, pf[2*i+1].y, pf[2*i+1].z, pf[2*i+1].w};
                uint4 hi, lo; pack8(f, hi, lo);
                uint32_t o = toff(r, ch);
                *(uint4*)(bp + o) = hi;
                *(uint4*)(bp + 16384 + o) = lo;
            }
        }

        // store this k-tile's scores
        float* base = abase + (size_t)t * 128;
        #pragma unroll
        for (int mi = 0; mi < 2; mi++) {
            #pragma unroll
            for (int ni = 0; ni < 8; ni++) {
                int row = wm * 32 + mi * 16 + qr;
                int col = wn * 64 + ni * 8 + qc;
                float2 v0 = make_float2(acc[mi][ni][0], acc[mi][ni][1]);
                float2 v1 = make_float2(acc[mi][ni][2], acc[mi][ni][3]);
                *(float2*)(base + (size_t)row * S_LEN + col) = v0;
                *(float2*)(base + (size_t)(row + 8) * S_LEN + col) = v1;
            }
        }
        __syncthreads();
    }
}

// -------------------------------------------------------------------------
// Kernel 2: per-row variance (ddof=1) -> tau -> softmax(scores/tau) in place.
// -------------------------------------------------------------------------
__global__ __launch_bounds__(256) void dsa_softvar_kernel(
    float* __restrict__ attn, float* __restrict__ tau_out)
{
    __shared__ float s[S_LEN];
    __shared__ float redA[8], redB[8], redC[8];
    __shared__ float bc[2];

    const size_t row = blockIdx.x;
    float* rowp = attn + row * (size_t)S_LEN;
    const int tid = threadIdx.x;
    const int lane = tid & 31, wid = tid >> 5;

    float4* s4 = (float4*)s;
    float4* r4 = (float4*)rowp;

    float sum = 0.f, sq = 0.f, mx = -3.402823466e38f;
    #pragma unroll
    for (int i = 0; i < 2; i++) {
        float4 f = r4[tid + i * 256];
        s4[tid + i * 256] = f;
        sum += f.x + f.y + f.z + f.w;
        sq = fmaf(f.x, f.x, sq); sq = fmaf(f.y, f.y, sq);
        sq = fmaf(f.z, f.z, sq); sq = fmaf(f.w, f.w, sq);
        mx = fmaxf(mx, fmaxf(fmaxf(f.x, f.y), fmaxf(f.z, f.w)));
    }
    #pragma unroll
    for (int o = 16; o; o >>= 1) {
        sum += __shfl_xor_sync(0xffffffffu, sum, o);
        sq  += __shfl_xor_sync(0xffffffffu, sq, o);
        mx   = fmaxf(mx, __shfl_xor_sync(0xffffffffu, mx, o));
    }
    if (lane == 0) { redA[wid] = sum; redB[wid] = sq; redC[wid] = mx; }
    __syncthreads();

    if (tid == 0) {
        float St = 0.f, Qt = 0.f, Mt = -3.402823466e38f;
        #pragma unroll
        for (int i = 0; i < 8; i++) {
            St += redA[i]; Qt += redB[i]; Mt = fmaxf(Mt, redC[i]);
        }
        float mean = St * (1.0f / S_LEN);
        float var  = (Qt - St * mean) * (1.0f / (S_LEN - 1));  // ddof=1
        float t = 1.0f / (1.0f + var);                          // BASE_TAU=1
        t = fmaxf(t, 0.3f);                                     // MIN_TAU
        bc[0] = 1.0f / t;
        bc[1] = Mt;
        tau_out[row] = t;
    }
    __syncthreads();

    const float itau = bc[0];
    const float m = bc[1];

    float lsum = 0.f;
    #pragma unroll
    for (int i = 0; i < 2; i++) {
        float4 f = s4[tid + i * 256];
        f.x = __expf((f.x - m) * itau);
        f.y = __expf((f.y - m) * itau);
        f.z = __expf((f.z - m) * itau);
        f.w = __expf((f.w - m) * itau);
        s4[tid + i * 256] = f;
        lsum += f.x + f.y + f.z + f.w;
    }
    #pragma unroll
    for (int o = 16; o; o >>= 1) lsum += __shfl_xor_sync(0xffffffffu, lsum, o);
    if (lane == 0) redA[wid] = lsum;
    __syncthreads();
    if (tid == 0) {
        float d = 0.f;
        #pragma unroll
        for (int i = 0; i < 8; i++) d += redA[i];
        bc[0] = 1.0f / d;
    }
    __syncthreads();

    const float rd = bc[0];
    #pragma unroll
    for (int i = 0; i < 2; i++) {
        float4 f = s4[tid + i * 256];
        f.x *= rd; f.y *= rd; f.z *= rd; f.w *= rd;
        r4[tid + i * 256] = f;
    }
}

// -------------------------------------------------------------------------
// Kernel 3: out = attn @ V via mma.sync bf16 hi/lo 3-term split.
// CTA: 128q x 64d, K=2048 in 32 chunks of 64, double-buffered SMEM.
// Term-major mma ordering. V frags via ldmatrix.x4.trans.
// Dynamic SMEM 96KB: 2 x [AHI 16K | ALO 16K | VHI 8K | VLO 8K].
// -------------------------------------------------------------------------
#define AV_SMEM 98304
#define AV_BUF  49152

__global__ __launch_bounds__(256, 2) void dsa_av_kernel(
    const float* __restrict__ attn, const float* __restrict__ v,
    float* __restrict__ out)
{
    extern __shared__ __align__(16) char sm[];
    const uint32_t sb = smem_u32(sm);

    const int tid = threadIdx.x, lane = tid & 31, wid = tid >> 5;
    const int bh = blockIdx.y, qt = blockIdx.x;

    const float* Ab = attn + ((size_t)bh * S_LEN + (size_t)qt * 128) * S_LEN;
    const float* Vb = v + (size_t)bh * S_LEN * D_DIM;

    const int wm = wid >> 1, wn = wid & 1;
    const int alr = lane & 7, alm = (lane >> 3) & 1, alk = lane >> 4;
    const int vkr_off = ((lane >> 3) & 1) * 8 + (lane & 7);
    const int vnc_off = lane >> 4;

    float acc[2][4][4] = {};

    auto load_chunk = [&](int chnk, int buf) {
        char* bp = sm + buf * AV_BUF;
        const int kk = chnk * 64;
        #pragma unroll
        for (int i = 0; i < 4; i++) {           // A: 128 x 64 f32
            int idx = tid + i * 256;
            int r = idx >> 3, ch = idx & 7;
            float4 f0 = *(const float4*)(Ab + (size_t)r * S_LEN + kk + ch * 8);
            float4 f1 = *(const float4*)(Ab + (size_t)r * S_LEN + kk + ch * 8 + 4);
            float f[8] = {f0.x, f0.y, f0.z, f0.w, f1.x, f1.y, f1.z, f1.w};
            uint4 hi, lo; pack8(f, hi, lo);
            uint32_t o = toff(r, ch);
            *(uint4*)(bp + o) = hi;
            *(uint4*)(bp + 16384 + o) = lo;
        }
        #pragma unroll
        for (int i = 0; i < 2; i++) {           // V: 64 x 64 f32
            int idx = tid + i * 256;
            int r = idx >> 3, ch = idx & 7;
            float4 f0 = *(const float4*)(Vb + (size_t)(kk + r) * D_DIM + ch * 8);
            float4 f1 = *(const float4*)(Vb + (size_t)(kk + r) * D_DIM + ch * 8 + 4);
            float f[8] = {f0.x, f0.y, f0.z, f0.w, f1.x, f1.y, f1.z, f1.w};
            uint4 hi, lo; pack8(f, hi, lo);
            uint32_t o = toff(r, ch);
            *(uint4*)(bp + 32768 + o) = hi;
            *(uint4*)(bp + 40960 + o) = lo;
        }
    };

    load_chunk(0, 0);
    __syncthreads();

    for (int chnk = 0; chnk < 32; chnk++) {
        if (chnk + 1 < 32) load_chunk(chnk + 1, (chnk + 1) & 1);

        const uint32_t bp = sb + (chnk & 1) * AV_BUF;
        const uint32_t AHI = bp, ALO = bp + 16384, VHI = bp + 32768, VLO = bp + 40960;

        #pragma unroll
        for (int ks = 0; ks < 4; ks++) {
            uint32_t ah[2][4], al[2][4];
            #pragma unroll
            for (int mi = 0; mi < 2; mi++) {
                int row = wm * 32 + mi * 16 + alr + alm * 8;
                uint32_t o = toff(row, ks * 2 + alk);
                ldmx4(ah[mi], AHI + o);
                ldmx4(al[mi], ALO + o);
            }
            uint32_t vh_[2][4], vl_[2][4];
            #pragma unroll
            for (int nj = 0; nj < 2; nj++) {
                int krow = ks * 16 + vkr_off;
                int nc = wn * 4 + nj * 2 + vnc_off;
                uint32_t o = toff(krow, nc);
                ldmx4t(vh_[nj], VHI + o);
                ldmx4t(vl_[nj], VLO + o);
            }
            #pragma unroll
            for (int mi = 0; mi < 2; mi++)
                #pragma unroll
                for (int nj = 0; nj < 2; nj++) {
                    mma_bf16(acc[mi][2*nj],   ah[mi], vh_[nj]);
                    mma_bf16(acc[mi][2*nj+1], ah[mi], vh_[nj] + 2);
                }
            #pragma unroll
            for (int mi = 0; mi < 2; mi++)
                #pragma unroll
                for (int nj = 0; nj < 2; nj++) {
                    mma_bf16(acc[mi][2*nj],   ah[mi], vl_[nj]);
                    mma_bf16(acc[mi][2*nj+1], ah[mi], vl_[nj] + 2);
                }
            #pragma unroll
            for (int mi = 0; mi < 2; mi++)
                #pragma unroll
                for (int nj = 0; nj < 2; nj++) {
                    mma_bf16(acc[mi][2*nj],   al[mi], vh_[nj]);
                    mma_bf16(acc[mi][2*nj+1], al[mi], vh_[nj] + 2);
                }
        }
        __syncthreads();
    }

    const int qr = lane >> 2, qc = (lane & 3) * 2;
    float* Ob = out + ((size_t)bh * S_LEN + (size_t)qt * 128) * D_DIM;
    #pragma unroll
    for (int mi = 0; mi < 2; mi++) {
        #pragma unroll
        for (int ni = 0; ni < 4; ni++) {
            int row = wm * 32 + mi * 16 + qr;
            int col = wn * 32 + ni * 8 + qc;
            float2 v0 = make_float2(acc[mi][ni][0], acc[mi][ni][1]);
            float2 v1 = make_float2(acc[mi][ni][2], acc[mi][ni][3]);
            *(float2*)(Ob + (size_t)row * D_DIM + col) = v0;
            *(float2*)(Ob + (size_t)(row + 8) * D_DIM + col) = v1;
        }
    }
}

// -------------------------------------------------------------------------
extern "C" void kernel_launch(void* const* d_in, const int* in_sizes, int n_in,
                              void* d_out, int out_size)
{
    const float* q = (const float*)d_in[0];
    const float* k = (const float*)d_in[1];
    const float* v = (const float*)d_in[2];

    float* outp = (float*)d_out;                                   // BH*S*D
    float* attn = outp + (size_t)BH * S_LEN * D_DIM;               // BH*S*S
    float* tau  = attn + (size_t)BH * S_LEN * S_LEN;               // BH*S

    cudaFuncSetAttribute(dsa_scores_kernel,
                         cudaFuncAttributeMaxDynamicSharedMemorySize, SC_SMEM);
    cudaFuncSetAttribute(dsa_av_kernel,
                         cudaFuncAttributeMaxDynamicSharedMemorySize, AV_SMEM);

    dsa_scores_kernel<<<dim3(S_LEN/128, BH), 256, SC_SMEM>>>(q, k, attn);
    dsa_softvar_kernel<<<BH * S_LEN, 256>>>(attn, tau);
    dsa_av_kernel<<<dim3(S_LEN/128, BH), 256, AV_SMEM>>>(attn, v, outp);
}

// round 11
// speedup vs baseline: 1.2981x; 1.1495x over previous
#include <cuda_runtime.h>
#include <cuda_bf16.h>
#include <cstdint>

// DynamicSparseAttention: B=4,H=16,S=2048,D=64
// d_out layout (f32): [out: BH*S*D][attn: BH*S*S][tau: BH*S]
#define S_LEN 2048
#define D_DIM 64
#define BH    64
#define NELEM (BH * S_LEN * D_DIM)   // 8388608

// pre-split bf16 hi/lo scratch (device globals: allocation-free scratch)
__device__ __align__(16) __nv_bfloat16 g_qhi[NELEM];
__device__ __align__(16) __nv_bfloat16 g_qlo[NELEM];
__device__ __align__(16) __nv_bfloat16 g_khi[NELEM];
__device__ __align__(16) __nv_bfloat16 g_klo[NELEM];
__device__ __align__(16) __nv_bfloat16 g_vhi[NELEM];
__device__ __align__(16) __nv_bfloat16 g_vlo[NELEM];

// ---------------------------------------------------------------- helpers
__device__ __forceinline__ uint32_t smem_u32(const void* p) {
    uint32_t a;
    asm("{ .reg .u64 t; cvta.to.shared.u64 t, %1; cvt.u32.u64 %0, t; }"
        : "=r"(a) : "l"(p));
    return a;
}

// 128B-row tile, 16B-chunk XOR swizzle
__device__ __forceinline__ uint32_t toff(int r, int ch) {
    return (uint32_t)(r * 128 + ((ch ^ (r & 7)) << 4));
}

__device__ __forceinline__ void ldmx4(uint32_t* r, uint32_t a) {
    asm volatile("ldmatrix.sync.aligned.m8n8.x4.shared.b16 {%0,%1,%2,%3}, [%4];"
        : "=r"(r[0]), "=r"(r[1]), "=r"(r[2]), "=r"(r[3]) : "r"(a));
}
__device__ __forceinline__ void ldmx4t(uint32_t* r, uint32_t a) {
    asm volatile("ldmatrix.sync.aligned.m8n8.x4.trans.shared.b16 {%0,%1,%2,%3}, [%4];"
        : "=r"(r[0]), "=r"(r[1]), "=r"(r[2]), "=r"(r[3]) : "r"(a));
}
__device__ __forceinline__ void mma_bf16(float* c, const uint32_t* a, const uint32_t* b) {
    asm volatile(
        "mma.sync.aligned.m16n8k16.row.col.f32.bf16.bf16.f32 "
        "{%0,%1,%2,%3}, {%4,%5,%6,%7}, {%8,%9}, {%0,%1,%2,%3};"
        : "+f"(c[0]), "+f"(c[1]), "+f"(c[2]), "+f"(c[3])
        : "r"(a[0]), "r"(a[1]), "r"(a[2]), "r"(a[3]), "r"(b[0]), "r"(b[1]));
}

__device__ __forceinline__ void cpa16(uint32_t dst, const void* src) {
    asm volatile("cp.async.cg.shared.global [%0], [%1], 16;"
                 :: "r"(dst), "l"(__cvta_generic_to_global(src)));
}
__device__ __forceinline__ void cpa_commit() {
    asm volatile("cp.async.commit_group;");
}
template <int N>
__device__ __forceinline__ void cpa_wait() {
    asm volatile("cp.async.wait_group %0;" :: "n"(N));
}

__device__ __forceinline__ uint32_t bfpair(float a, float b) {
    __nv_bfloat162 t;
    t.x = __float2bfloat16(a);
    t.y = __float2bfloat16(b);
    return *reinterpret_cast<uint32_t*>(&t);
}
// split 8 floats into 8 bf16 hi (uint4) + 8 bf16 lo (uint4)
__device__ __forceinline__ void pack8(const float* f, uint4& hi, uint4& lo) {
    float r[8];
    #pragma unroll
    for (int j = 0; j < 8; j++)
        r[j] = f[j] - __bfloat162float(__float2bfloat16(f[j]));
    hi = make_uint4(bfpair(f[0], f[1]), bfpair(f[2], f[3]),
                    bfpair(f[4], f[5]), bfpair(f[6], f[7]));
    lo = make_uint4(bfpair(r[0], r[1]), bfpair(r[2], r[3]),
                    bfpair(r[4], r[5]), bfpair(r[6], r[7]));
}
// split float4 -> uint2 hi + uint2 lo
__device__ __forceinline__ void split4(float4 f, uint2& hi, uint2& lo) {
    float a[4] = {f.x, f.y, f.z, f.w};
    float r[4];
    #pragma unroll
    for (int j = 0; j < 4; j++)
        r[j] = a[j] - __bfloat162float(__float2bfloat16(a[j]));
    hi = make_uint2(bfpair(a[0], a[1]), bfpair(a[2], a[3]));
    lo = make_uint2(bfpair(r[0], r[1]), bfpair(r[2], r[3]));
}

// -------------------------------------------------------------------------
// Kernel 0: pre-split Q*0.125, K, V into bf16 hi/lo scratch.
// -------------------------------------------------------------------------
__global__ __launch_bounds__(256) void dsa_prep(
    const float* __restrict__ q, const float* __restrict__ k,
    const float* __restrict__ v)
{
    const int stride = gridDim.x * 256;
    const float4* q4 = (const float4*)q;
    const float4* k4 = (const float4*)k;
    const float4* v4 = (const float4*)v;
    uint2* qh = (uint2*)g_qhi; uint2* ql = (uint2*)g_qlo;
    uint2* kh = (uint2*)g_khi; uint2* kl = (uint2*)g_klo;
    uint2* vh = (uint2*)g_vhi; uint2* vl = (uint2*)g_vlo;

    for (int i = blockIdx.x * 256 + threadIdx.x; i < NELEM / 4; i += stride) {
        float4 fq = q4[i];
        fq.x *= 0.125f; fq.y *= 0.125f; fq.z *= 0.125f; fq.w *= 0.125f;
        uint2 hi, lo;
        split4(fq, hi, lo); qh[i] = hi; ql[i] = lo;
        split4(k4[i], hi, lo); kh[i] = hi; kl[i] = lo;
        split4(v4[i], hi, lo); vh[i] = hi; vl[i] = lo;
    }
}

// -------------------------------------------------------------------------
// Kernel 1: scores = (Q*scale) K^T, mma.sync bf16 hi/lo 3-term split.
// CTA = 128-row q-stripe, loops over 16 k-tiles of 128. 512 threads,
// 16 warps (4m x 4n), warp tile 32x32. A frags cached in regs; K tiles
// arrive pre-split via cp.async (double-buffered). SMEM 96KB.
// -------------------------------------------------------------------------
#define SC_SMEM 98304
__global__ __launch_bounds__(512) void dsa_scores_kernel(float* __restrict__ attn)
{
    extern __shared__ __align__(16) char sm[];
    const uint32_t sb = smem_u32(sm);
    const uint32_t QHI = 0, QLO = 16384;      // K bufs at 32768 + b*32768

    const int tid = threadIdx.x, lane = tid & 31, wid = tid >> 5;
    const int qt = blockIdx.x, bh = blockIdx.y;

    const __nv_bfloat16* Qh = g_qhi + ((size_t)bh * S_LEN + (size_t)qt * 128) * D_DIM;
    const __nv_bfloat16* Ql = g_qlo + ((size_t)bh * S_LEN + (size_t)qt * 128) * D_DIM;
    const __nv_bfloat16* Kh = g_khi + (size_t)bh * S_LEN * D_DIM;
    const __nv_bfloat16* Kl = g_klo + (size_t)bh * S_LEN * D_DIM;

    // group 0: Q hi/lo + K tile 0
    #pragma unroll
    for (int i = 0; i < 2; i++) {
        int idx = tid + i * 512;
        int r = idx >> 3, ch = idx & 7;
        uint32_t o = toff(r, ch);
        cpa16(sb + QHI + o, Qh + r * 64 + ch * 8);
        cpa16(sb + QLO + o, Ql + r * 64 + ch * 8);
        cpa16(sb + 32768 + o, Kh + r * 64 + ch * 8);
        cpa16(sb + 32768 + 16384 + o, Kl + r * 64 + ch * 8);
    }
    cpa_commit();
    // group 1: K tile 1
    #pragma unroll
    for (int i = 0; i < 2; i++) {
        int idx = tid + i * 512;
        int r = idx >> 3, ch = idx & 7;
        uint32_t o = toff(r, ch);
        cpa16(sb + 65536 + o, Kh + (size_t)(128 + r) * 64 + ch * 8);
        cpa16(sb + 65536 + 16384 + o, Kl + (size_t)(128 + r) * 64 + ch * 8);
    }
    cpa_commit();
    cpa_wait<1>();          // group 0 (Q + K0) complete
    __syncthreads();

    const int wm = wid >> 2, wn = wid & 3;
    const int alr = lane & 7, alm = (lane >> 3) & 1, alk = lane >> 4;
    const int brow_off = ((lane >> 4) << 3) + (lane & 7);
    const int bchk_off = (lane >> 3) & 1;

    // A fragments cached in registers for the whole kernel
    uint32_t ah[4][2][4], al[4][2][4];
    #pragma unroll
    for (int ks = 0; ks < 4; ks++)
        #pragma unroll
        for (int mi = 0; mi < 2; mi++) {
            int row = wm * 32 + mi * 16 + alr + alm * 8;
            uint32_t o = toff(row, ks * 2 + alk);
            ldmx4(ah[ks][mi], sb + QHI + o);
            ldmx4(al[ks][mi], sb + QLO + o);
        }

    const int qr = lane >> 2, qc = (lane & 3) * 2;
    float* abase = attn + ((size_t)bh * S_LEN + (size_t)qt * 128) * S_LEN;

    for (int t = 0; t < 16; t++) {
        const uint32_t KB = sb + 32768 + (uint32_t)(t & 1) * 32768;

        float acc[2][4][4] = {};
        #pragma unroll
        for (int ks = 0; ks < 4; ks++) {
            uint32_t bh_[2][4], bl_[2][4];
            #pragma unroll
            for (int nj = 0; nj < 2; nj++) {
                int row = wn * 32 + nj * 16 + brow_off;
                uint32_t o = toff(row, ks * 2 + bchk_off);
                ldmx4(bh_[nj], KB + o);
                ldmx4(bl_[nj], KB + 16384 + o);
            }
            #pragma unroll
            for (int mi = 0; mi < 2; mi++)
                #pragma unroll
                for (int nj = 0; nj < 2; nj++) {
                    mma_bf16(acc[mi][2*nj],   ah[ks][mi], bh_[nj]);
                    mma_bf16(acc[mi][2*nj+1], ah[ks][mi], bh_[nj] + 2);
                }
            #pragma unroll
            for (int mi = 0; mi < 2; mi++)
                #pragma unroll
                for (int nj = 0; nj < 2; nj++) {
                    mma_bf16(acc[mi][2*nj],   ah[ks][mi], bl_[nj]);
                    mma_bf16(acc[mi][2*nj+1], ah[ks][mi], bl_[nj] + 2);
                }
            #pragma unroll
            for (int mi = 0; mi < 2; mi++)
                #pragma unroll
                for (int nj = 0; nj < 2; nj++) {
                    mma_bf16(acc[mi][2*nj],   al[ks][mi], bh_[nj]);
                    mma_bf16(acc[mi][2*nj+1], al[ks][mi], bh_[nj] + 2);
                }
        }

        // store this k-tile's scores
        float* base = abase + (size_t)t * 128;
        #pragma unroll
        for (int mi = 0; mi < 2; mi++) {
            #pragma unroll
            for (int ni = 0; ni < 4; ni++) {
                int row = wm * 32 + mi * 16 + qr;
                int col = wn * 32 + ni * 8 + qc;
                float2 v0 = make_float2(acc[mi][ni][0], acc[mi][ni][1]);
                float2 v1 = make_float2(acc[mi][ni][2], acc[mi][ni][3]);
                *(float2*)(base + (size_t)row * S_LEN + col) = v0;
                *(float2*)(base + (size_t)(row + 8) * S_LEN + col) = v1;
            }
        }
        __syncthreads();   // all reads of buf[t&1] done before refill

        if (t + 2 < 16) {
            const __nv_bfloat16* th = Kh + (size_t)(t + 2) * 128 * 64;
            const __nv_bfloat16* tl = Kl + (size_t)(t + 2) * 128 * 64;
            uint32_t dst = sb + 32768 + (uint32_t)(t & 1) * 32768;
            #pragma unroll
            for (int i = 0; i < 2; i++) {
                int idx = tid + i * 512;
                int r = idx >> 3, ch = idx & 7;
                uint32_t o = toff(r, ch);
                cpa16(dst + o, th + r * 64 + ch * 8);
                cpa16(dst + 16384 + o, tl + r * 64 + ch * 8);
            }
            cpa_commit();
            cpa_wait<1>();   // K(t+1) ready
        } else {
            cpa_wait<0>();
        }
        __syncthreads();
    }
}

// -------------------------------------------------------------------------
// Kernel 2: per-row variance (ddof=1) -> tau -> softmax(scores/tau) in place.
// Warp-per-row, row in REGISTERS (16 float4/lane). No smem, no barriers.
// -------------------------------------------------------------------------
__global__ __launch_bounds__(256, 2) void dsa_softvar_kernel(
    float* __restrict__ attn, float* __restrict__ tau_out)
{
    const int lane = threadIdx.x & 31;
    const int w = threadIdx.x >> 5;
    const size_t row = (size_t)blockIdx.x * 8 + w;
    float4* r4 = (float4*)(attn + row * S_LEN);

    float4 d[16];
    float sum = 0.f, sq = 0.f, mx = -3.402823466e38f;
    #pragma unroll
    for (int i = 0; i < 16; i++) {
        float4 f = r4[lane + 32 * i];
        d[i] = f;
        sum += f.x + f.y + f.z + f.w;
        sq = fmaf(f.x, f.x, sq); sq = fmaf(f.y, f.y, sq);
        sq = fmaf(f.z, f.z, sq); sq = fmaf(f.w, f.w, sq);
        mx = fmaxf(mx, fmaxf(fmaxf(f.x, f.y), fmaxf(f.z, f.w)));
    }
    #pragma unroll
    for (int o = 16; o; o >>= 1) {
        sum += __shfl_xor_sync(0xffffffffu, sum, o);
        sq  += __shfl_xor_sync(0xffffffffu, sq, o);
        mx   = fmaxf(mx, __shfl_xor_sync(0xffffffffu, mx, o));
    }

    float mean = sum * (1.0f / S_LEN);
    float var  = (sq - sum * mean) * (1.0f / (S_LEN - 1));  // ddof=1
    float tau  = fmaxf(1.0f / (1.0f + var), 0.3f);          // BASE=1, MIN=0.3
    float itau = 1.0f / tau;
    if (lane == 0) tau_out[row] = tau;

    float ls = 0.f;
    #pragma unroll
    for (int i = 0; i < 16; i++) {
        float4 f = d[i];
        f.x = __expf((f.x - mx) * itau);
        f.y = __expf((f.y - mx) * itau);
        f.z = __expf((f.z - mx) * itau);
        f.w = __expf((f.w - mx) * itau);
        d[i] = f;
        ls += f.x + f.y + f.z + f.w;
    }
    #pragma unroll
    for (int o = 16; o; o >>= 1) ls += __shfl_xor_sync(0xffffffffu, ls, o);
    const float rd = 1.0f / ls;

    #pragma unroll
    for (int i = 0; i < 16; i++) {
        float4 f = d[i];
        f.x *= rd; f.y *= rd; f.z *= rd; f.w *= rd;
        r4[lane + 32 * i] = f;
    }
}

// -------------------------------------------------------------------------
// Kernel 3: out = attn @ V, mma.sync bf16 hi/lo 3-term split.
// CTA: 128q x 64d, K=2048 in 32 chunks of 64, double-buffered SMEM.
// A: LDG-prefetch + pack + STS; V: cp.async from pre-split scratch.
// Dynamic SMEM 96KB: 2 x [AHI 16K | ALO 16K | VHI 8K | VLO 8K].
// -------------------------------------------------------------------------
#define AV_SMEM 98304
#define AV_BUF  49152

__global__ __launch_bounds__(256, 2) void dsa_av_kernel(
    const float* __restrict__ attn, float* __restrict__ out)
{
    extern __shared__ __align__(16) char sm[];
    const uint32_t sb = smem_u32(sm);

    const int tid = threadIdx.x, lane = tid & 31, wid = tid >> 5;
    const int bh = blockIdx.y, qt = blockIdx.x;

    const float* Ab = attn + ((size_t)bh * S_LEN + (size_t)qt * 128) * S_LEN;
    const __nv_bfloat16* Vh = g_vhi + (size_t)bh * S_LEN * D_DIM;
    const __nv_bfloat16* Vl = g_vlo + (size_t)bh * S_LEN * D_DIM;

    const int wm = wid >> 1, wn = wid & 1;
    const int alr = lane & 7, alm = (lane >> 3) & 1, alk = lane >> 4;
    const int vkr_off = ((lane >> 3) & 1) * 8 + (lane & 7);
    const int vnc_off = lane >> 4;

    float acc[2][4][4] = {};
    float4 pf[8];

    auto ldgA = [&](int kk) {
        #pragma unroll
        for (int i = 0; i < 4; i++) {
            int idx = tid + i * 256;
            int r = idx >> 3, ch = idx & 7;
            pf[2*i]   = *(const float4*)(Ab + (size_t)r * S_LEN + kk + ch * 8);
            pf[2*i+1] = *(const float4*)(Ab + (size_t)r * S_LEN + kk + ch * 8 + 4);
        }
    };
    auto cpaV = [&](int kk, uint32_t bp) {
        #pragma unroll
        for (int i = 0; i < 2; i++) {
            int idx = tid + i * 256;
            int r = idx >> 3, ch = idx & 7;
            uint32_t o = toff(r, ch);
            cpa16(bp + 32768 + o, Vh + (size_t)(kk + r) * 64 + ch * 8);
            cpa16(bp + 40960 + o, Vl + (size_t)(kk + r) * 64 + ch * 8);
        }
    };
    auto stsA = [&](char* bpc) {
        #pragma unroll
        for (int i = 0; i < 4; i++) {
            int idx = tid + i * 256;
            int r = idx >> 3, ch = idx & 7;
            float f[8] = {pf[2*i].x, pf[2*i].y, pf[2*i].z, pf[2*i].w,
                          pf[2*i+1].x, pf[2*i+1].y, pf[2*i+1].z, pf[2*i+1].w};
            uint4 hi, lo; pack8(f, hi, lo);
            uint32_t o = toff(r, ch);
            *(uint4*)(bpc + o) = hi;
            *(uint4*)(bpc + 16384 + o) = lo;
        }
    };

    // prologue: chunk 0
    ldgA(0);
    cpaV(0, sb);
    cpa_commit();
    stsA(sm);
    cpa_wait<0>();
    __syncthreads();

    for (int t = 0; t < 32; t++) {
        if (t + 1 < 32) {
            ldgA((t + 1) * 64);
            cpaV((t + 1) * 64, sb + (uint32_t)((t + 1) & 1) * AV_BUF);
            cpa_commit();
        }

        const uint32_t bp = sb + (uint32_t)(t & 1) * AV_BUF;
        const uint32_t AHI = bp, ALO = bp + 16384, VHI = bp + 32768, VLO = bp + 40960;

        #pragma unroll
        for (int ks = 0; ks < 4; ks++) {
            uint32_t ah[2][4], al[2][4];
            #pragma unroll
            for (int mi = 0; mi < 2; mi++) {
                int row = wm * 32 + mi * 16 + alr + alm * 8;
                uint32_t o = toff(row, ks * 2 + alk);
                ldmx4(ah[mi], AHI + o);
                ldmx4(al[mi], ALO + o);
            }
            uint32_t vh_[2][4], vl_[2][4];
            #pragma unroll
            for (int nj = 0; nj < 2; nj++) {
                int krow = ks * 16 + vkr_off;
                int nc = wn * 4 + nj * 2 + vnc_off;
                uint32_t o = toff(krow, nc);
                ldmx4t(vh_[nj], VHI + o);
                ldmx4t(vl_[nj], VLO + o);
            }
            #pragma unroll
            for (int mi = 0; mi < 2; mi++)
                #pragma unroll
                for (int nj = 0; nj < 2; nj++) {
                    mma_bf16(acc[mi][2*nj],   ah[mi], vh_[nj]);
                    mma_bf16(acc[mi][2*nj+1], ah[mi], vh_[nj] + 2);
                }
            #pragma unroll
            for (int mi = 0; mi < 2; mi++)
                #pragma unroll
                for (int nj = 0; nj < 2; nj++) {
                    mma_bf16(acc[mi][2*nj],   ah[mi], vl_[nj]);
                    mma_bf16(acc[mi][2*nj+1], ah[mi], vl_[nj] + 2);
                }
            #pragma unroll
            for (int mi = 0; mi < 2; mi++)
                #pragma unroll
                for (int nj = 0; nj < 2; nj++) {
                    mma_bf16(acc[mi][2*nj],   al[mi], vh_[nj]);
                    mma_bf16(acc[mi][2*nj+1], al[mi], vh_[nj] + 2);
                }
        }

        if (t + 1 < 32) {
            stsA(sm + (size_t)((t + 1) & 1) * AV_BUF);
            cpa_wait<0>();
        }
        __syncthreads();
    }

    const int qr = lane >> 2, qc = (lane & 3) * 2;
    float* Ob = out + ((size_t)bh * S_LEN + (size_t)qt * 128) * D_DIM;
    #pragma unroll
    for (int mi = 0; mi < 2; mi++) {
        #pragma unroll
        for (int ni = 0; ni < 4; ni++) {
            int row = wm * 32 + mi * 16 + qr;
            int col = wn * 32 + ni * 8 + qc;
            float2 v0 = make_float2(acc[mi][ni][0], acc[mi][ni][1]);
            float2 v1 = make_float2(acc[mi][ni][2], acc[mi][ni][3]);
            *(float2*)(Ob + (size_t)row * D_DIM + col) = v0;
            *(float2*)(Ob + (size_t)(row + 8) * D_DIM + col) = v1;
        }
    }
}

// -------------------------------------------------------------------------
extern "C" void kernel_launch(void* const* d_in, const int* in_sizes, int n_in,
                              void* d_out, int out_size)
{
    const float* q = (const float*)d_in[0];
    const float* k = (const float*)d_in[1];
    const float* v = (const float*)d_in[2];

    float* outp = (float*)d_out;                                   // BH*S*D
    float* attn = outp + (size_t)BH * S_LEN * D_DIM;               // BH*S*S
    float* tau  = attn + (size_t)BH * S_LEN * S_LEN;               // BH*S

    cudaFuncSetAttribute(dsa_scores_kernel,
                         cudaFuncAttributeMaxDynamicSharedMemorySize, SC_SMEM);
    cudaFuncSetAttribute(dsa_av_kernel,
                         cudaFuncAttributeMaxDynamicSharedMemorySize, AV_SMEM);

    dsa_prep<<<2048, 256>>>(q, k, v);
    dsa_scores_kernel<<<dim3(S_LEN / 128, BH), 512, SC_SMEM>>>(attn);
    dsa_softvar_kernel<<<BH * S_LEN / 8, 256>>>(attn, tau);
    dsa_av_kernel<<<dim3(S_LEN / 128, BH), 256, AV_SMEM>>>(attn, outp);
}